// round 12
// baseline (speedup 1.0000x reference)
#include <cuda_runtime.h>
#include <cuda_bf16.h>

#define NN 50000
#define D 128
#define LAY 3
#define RK 16
#define NE 1600000
#define NB 148
#define NTHREADS (NB * 1024)
#define NWARPS (NB * 32)
#define CHUNK 338                    // 148*338 = 50024 >= 50000
#define NTILES ((NN + 127) / 128)    // 391
#define SPITCH 136                   // bf16 smem row pitch
#define SA_BYTES (128 * SPITCH * 2)  // 34816
#define SMEM_BYTES (2 * SA_BYTES + 512)

// ---------------- static device scratch ----------------
static __device__ int d_cnt[NN];          // zero at entry (BSS / re-zeroed each run)
static __device__ int d_rowptr[NN + 1];
static __device__ int d_cursor[NN];
static __device__ int d_btot[NB];
static __device__ int d_boff[NB];
static __device__ __align__(16) uint2 d_edge[NE];             // {col, val bits}
static __device__ __align__(16) __nv_bfloat16 d_hb[NN * D];   // h (bf16)
static __device__ __align__(16) float d_zsum[D];

static __device__ unsigned bar_count = 0;
static __device__ volatile unsigned bar_gen = 0;

__device__ __forceinline__ void gridbar() {
    __syncthreads();                      // intra-block visibility of all prior accesses
    if (threadIdx.x == 0) {
        __threadfence();                  // leader release (publishes block's writes)
        unsigned g = bar_gen;
        if (atomicAdd(&bar_count, 1u) == NB - 1) {
            bar_count = 0;
            __threadfence();
            bar_gen = g + 1;
        } else {
            while (bar_gen == g) { __nanosleep(64); }
        }
        __threadfence();                  // leader acquire (invalidates SM L1D)
    }
    __syncthreads();
}

__device__ __forceinline__ float eluf(float t) {
    return t > 0.f ? t : (__expf(t) - 1.f);
}

__device__ __forceinline__ void ldm_x4(unsigned r[4], unsigned addr) {
    asm volatile("ldmatrix.sync.aligned.m8n8.x4.shared.b16 {%0,%1,%2,%3}, [%4];"
                 : "=r"(r[0]), "=r"(r[1]), "=r"(r[2]), "=r"(r[3]) : "r"(addr));
}

__device__ __forceinline__ void mma_bf16(float c[4], const unsigned a[4],
                                         unsigned b0, unsigned b1) {
    asm volatile("mma.sync.aligned.m16n8k16.row.col.f32.bf16.bf16.f32 "
                 "{%0,%1,%2,%3}, {%4,%5,%6,%7}, {%8,%9}, {%0,%1,%2,%3};"
                 : "+f"(c[0]), "+f"(c[1]), "+f"(c[2]), "+f"(c[3])
                 : "r"(a[0]), "r"(a[1]), "r"(a[2]), "r"(a[3]), "r"(b0), "r"(b1));
}

__global__ void __launch_bounds__(1024, 1)
k_all(const int* __restrict__ rows, const int* __restrict__ cols,
      const float* __restrict__ vals, const float* __restrict__ feats,
      const float* __restrict__ gW, const float* __restrict__ gb,
      const float* __restrict__ fc1W, const float* __restrict__ fc1b,
      const float* __restrict__ frW, const float* __restrict__ frb,
      const float* __restrict__ fcW, const float* __restrict__ fcb,
      const float* __restrict__ ini, float* __restrict__ out)
{
    extern __shared__ float sm[];
    __nv_bfloat16* sA = (__nv_bfloat16*)sm;
    __nv_bfloat16* sB = (__nv_bfloat16*)((char*)sm + SA_BYTES);
    float* scol = (float*)((char*)sm + 2 * SA_BYTES);   // 128 floats

    const int tid  = threadIdx.x;
    const int bid  = blockIdx.x;
    const int gtid = bid * 1024 + tid;
    const int lane = tid & 31;
    const int wid  = tid >> 5;
    const int gwarp = bid * 32 + wid;

    // ---------- phase 1: histogram (d_cnt is zero at entry) ----------
    for (int e4 = gtid; e4 < NE / 4; e4 += NTHREADS) {
        int4 r4 = *(const int4*)(rows + e4 * 4);
        atomicAdd(&d_cnt[r4.x], 1);
        atomicAdd(&d_cnt[r4.y], 1);
        atomicAdd(&d_cnt[r4.z], 1);
        atomicAdd(&d_cnt[r4.w], 1);
    }
    gridbar();

    // ---------- scan A (+ zero zsum for this run) ----------
    {
        int* s = (int*)sm;
        int i = bid * CHUNK + tid;
        int v = (tid < CHUNK && i < NN) ? d_cnt[i] : 0;
        s[tid] = v;
        __syncthreads();
        #pragma unroll
        for (int off = 1; off < 1024; off <<= 1) {
            int a = (tid >= off) ? s[tid - off] : 0;
            __syncthreads();
            s[tid] += a;
            __syncthreads();
        }
        if (tid < CHUNK && i < NN) d_rowptr[i] = s[tid] - v;
        if (tid == 0) d_btot[bid] = s[1023];
    }
    if (gtid < D) d_zsum[gtid] = 0.f;
    gridbar();

    // ---------- scan B (block 0) || colsum + feats->bf16 (blocks 1..147) ----------
    if (bid == 0) {
        int* s = (int*)sm;
        int v = (tid < NB) ? d_btot[tid] : 0;
        s[tid] = v;
        __syncthreads();
        #pragma unroll
        for (int off = 1; off < 1024; off <<= 1) {
            int a = (tid >= off) ? s[tid - off] : 0;
            __syncthreads();
            s[tid] += a;
            __syncthreads();
        }
        if (tid < NB) d_boff[tid] = s[tid] - v;
        if (tid == 0) d_rowptr[NN] = s[1023];
    } else {
        if (tid < D) scol[tid] = 0.f;
        __syncthreads();
        float4 cacc = make_float4(0.f, 0.f, 0.f, 0.f);
        int cwarp = (bid - 1) * 32 + wid;
        for (int r = cwarp; r < NN; r += 147 * 32) {
            float4 v = *(const float4*)(feats + (size_t)r * D + lane * 4);
            cacc.x += v.x; cacc.y += v.y; cacc.z += v.z; cacc.w += v.w;
            __nv_bfloat162* dst = (__nv_bfloat162*)(d_hb + (size_t)r * D + lane * 4);
            dst[0] = __floats2bfloat162_rn(v.x, v.y);
            dst[1] = __floats2bfloat162_rn(v.z, v.w);
        }
        atomicAdd(&scol[lane * 4 + 0], cacc.x);
        atomicAdd(&scol[lane * 4 + 1], cacc.y);
        atomicAdd(&scol[lane * 4 + 2], cacc.z);
        atomicAdd(&scol[lane * 4 + 3], cacc.w);
        __syncthreads();
        if (tid < D) atomicAdd(&d_zsum[tid], scol[tid]);
    }
    gridbar();

    // ---------- scan C: finalize rowptr/cursor; re-zero d_cnt for next replay ----------
    {
        int off = d_boff[bid];
        int i = bid * CHUNK + tid;
        if (tid < CHUNK && i < NN) {
            int val = d_rowptr[i] + off;
            d_rowptr[i] = val;
            d_cursor[i] = val;
        }
    }
    for (int i = gtid; i < NN; i += NTHREADS) d_cnt[i] = 0;
    gridbar();

    // ---------- scatter (packed edges) ----------
    for (int e4 = gtid; e4 < NE / 4; e4 += NTHREADS) {
        int4   r4 = *(const int4*)(rows + e4 * 4);
        int4   c4 = *(const int4*)(cols + e4 * 4);
        float4 v4 = *(const float4*)(vals + e4 * 4);
        int p;
        p = atomicAdd(&d_cursor[r4.x], 1); d_edge[p] = make_uint2((unsigned)c4.x, __float_as_uint(v4.x));
        p = atomicAdd(&d_cursor[r4.y], 1); d_edge[p] = make_uint2((unsigned)c4.y, __float_as_uint(v4.y));
        p = atomicAdd(&d_cursor[r4.z], 1); d_edge[p] = make_uint2((unsigned)c4.z, __float_as_uint(v4.z));
        p = atomicAdd(&d_cursor[r4.w], 1); d_edge[p] = make_uint2((unsigned)c4.w, __float_as_uint(v4.w));
    }
    gridbar();

    // ---------- GNN layers: fused SpMM(tile->smem) + tensor-core GEMM ----------
    const unsigned sA_base = (unsigned)__cvta_generic_to_shared(sA);
    const unsigned sB_base = (unsigned)__cvta_generic_to_shared(sB);
    const int wm = wid >> 2, wn = wid & 3;

    for (int l = 0; l < LAY; l++) {
        // W_l -> sB (bf16), block-local
        #pragma unroll
        for (int t = 0; t < 4; t++) {
            int j = tid + t * 1024;          // 4096 groups of 4 floats
            int row = j >> 5, seg = j & 31;
            float4 v = *(const float4*)(gW + (size_t)l * D * D + row * D + seg * 4);
            __nv_bfloat162* dst = (__nv_bfloat162*)(sB + row * SPITCH + seg * 4);
            dst[0] = __floats2bfloat162_rn(v.x, v.y);
            dst[1] = __floats2bfloat162_rn(v.z, v.w);
        }
        if (tid < D) scol[tid] = 0.f;
        float bias[4][2];
        #pragma unroll
        for (int f = 0; f < 4; f++) {
            int nb = wn * 32 + f * 8 + (lane & 3) * 2;
            bias[f][0] = gb[l * D + nb];
            bias[f][1] = gb[l * D + nb + 1];
        }
        __syncthreads();

        for (int tile = bid; tile < NTILES; tile += NB) {
            int rb = tile * 128;

            // --- SpMM: 4 rows per warp, gather bf16 h, write bf16 into sA ---
            #pragma unroll
            for (int rr = 0; rr < 4; rr++) {
                int lr = wid + rr * 32;
                int row = rb + lr;
                float4 acc = make_float4(0.f, 0.f, 0.f, 0.f);
                if (row < NN) {
                    int e0 = d_rowptr[row], e1 = d_rowptr[row + 1];
                    for (int e = e0; e < e1; e += 32) {
                        int idx = e + lane;
                        uint2 ev = make_uint2(0u, 0u);
                        if (idx < e1) ev = d_edge[idx];
                        int nb2 = e1 - e; if (nb2 > 32) nb2 = 32;
                        int full = nb2 & ~7;
                        int jb = 0;
                        // full 8-groups: unpredicated (common path, MLP=8)
                        for (; jb < full; jb += 8) {
                            uint2 hv[8]; float vv[8];
                            #pragma unroll
                            for (int u = 0; u < 8; u++) {
                                int c       = __shfl_sync(0xffffffffu, (int)ev.x, jb + u);
                                unsigned vb = __shfl_sync(0xffffffffu, ev.y, jb + u);
                                vv[u] = __uint_as_float(vb);
                                hv[u] = *(const uint2*)(d_hb + (size_t)c * D + lane * 4);
                            }
                            #pragma unroll
                            for (int u = 0; u < 8; u++) {
                                float2 f0 = __bfloat1622float2(*(const __nv_bfloat162*)&hv[u].x);
                                float2 f1 = __bfloat1622float2(*(const __nv_bfloat162*)&hv[u].y);
                                acc.x += vv[u] * f0.x; acc.y += vv[u] * f0.y;
                                acc.z += vv[u] * f1.x; acc.w += vv[u] * f1.y;
                            }
                        }
                        // tail group: predicated loads only here
                        if (jb < nb2) {
                            uint2 hv[8]; float vv[8];
                            #pragma unroll
                            for (int u = 0; u < 8; u++) {
                                int c       = __shfl_sync(0xffffffffu, (int)ev.x, jb + u);
                                unsigned vb = __shfl_sync(0xffffffffu, ev.y, jb + u);
                                vv[u] = __uint_as_float(vb);
                                if (jb + u < nb2)
                                    hv[u] = *(const uint2*)(d_hb + (size_t)c * D + lane * 4);
                                else
                                    hv[u] = make_uint2(0u, 0u);
                            }
                            #pragma unroll
                            for (int u = 0; u < 8; u++) {
                                float2 f0 = __bfloat1622float2(*(const __nv_bfloat162*)&hv[u].x);
                                float2 f1 = __bfloat1622float2(*(const __nv_bfloat162*)&hv[u].y);
                                acc.x += vv[u] * f0.x; acc.y += vv[u] * f0.y;
                                acc.z += vv[u] * f1.x; acc.w += vv[u] * f1.y;
                            }
                        }
                    }
                }
                __nv_bfloat162* dst = (__nv_bfloat162*)(sA + lr * SPITCH + lane * 4);
                dst[0] = __floats2bfloat162_rn(acc.x, acc.y);
                dst[1] = __floats2bfloat162_rn(acc.z, acc.w);
            }
            __syncthreads();   // sA complete

            // --- GEMM on tile ---
            float c[4][4];
            #pragma unroll
            for (int f = 0; f < 4; f++)
                #pragma unroll
                for (int q = 0; q < 4; q++) c[f][q] = 0.f;

            #pragma unroll
            for (int ks = 0; ks < 8; ks++) {
                int k0 = ks * 16;
                unsigned a[4];
                unsigned aaddr = sA_base +
                    ((wm * 16 + (lane & 15)) * SPITCH + k0 + (lane >> 4) * 8) * 2;
                ldm_x4(a, aaddr);
                #pragma unroll
                for (int half = 0; half < 2; half++) {
                    int nbase = wn * 32 + half * 16;
                    int grp = lane >> 3;
                    int nrow = nbase + ((grp & 2) << 2) + (lane & 7);
                    int koff = k0 + ((grp & 1) << 3);
                    unsigned b[4];
                    unsigned baddr = sB_base + (nrow * SPITCH + koff) * 2;
                    ldm_x4(b, baddr);
                    mma_bf16(c[half * 2 + 0], a, b[0], b[1]);
                    mma_bf16(c[half * 2 + 1], a, b[2], b[3]);
                }
            }
            __syncthreads();   // done reading sA

            // --- epilogue: bias + ELU -> bf16 h, column sums ---
            int r0g = rb + wm * 16 + (lane >> 2);
            int r1g = r0g + 8;
            bool v0 = r0g < NN, v1 = r1g < NN;
            #pragma unroll
            for (int f = 0; f < 4; f++) {
                int nb = wn * 32 + f * 8 + (lane & 3) * 2;
                float o0 = eluf(c[f][0] + bias[f][0]), o1 = eluf(c[f][1] + bias[f][1]);
                float o2 = eluf(c[f][2] + bias[f][0]), o3 = eluf(c[f][3] + bias[f][1]);
                if (v0) *(__nv_bfloat162*)(d_hb + (size_t)r0g * D + nb) =
                            __floats2bfloat162_rn(o0, o1);
                if (v1) *(__nv_bfloat162*)(d_hb + (size_t)r1g * D + nb) =
                            __floats2bfloat162_rn(o2, o3);
                float s0 = (v0 ? o0 : 0.f) + (v1 ? o2 : 0.f);
                float s1 = (v0 ? o1 : 0.f) + (v1 ? o3 : 0.f);
                #pragma unroll
                for (int off = 4; off < 32; off <<= 1) {
                    s0 += __shfl_xor_sync(0xffffffffu, s0, off);
                    s1 += __shfl_xor_sync(0xffffffffu, s1, off);
                }
                if (lane < 4) {
                    atomicAdd(&scol[nb], s0);
                    atomicAdd(&scol[nb + 1], s1);
                }
            }
        }
        __syncthreads();
        if (tid < D) atomicAdd(&d_zsum[tid], scol[tid]);
        gridbar();
    }

    // ---------- tail ----------
    float* s_hz   = sm;
    float* s_wcol = sm + 128;
    {
        const float inv = 1.0f / ((float)(LAY + 1) * (float)NN);
        float4 z4 = *(const float4*)(d_zsum + lane * 4);
        z4.x *= inv; z4.y *= inv; z4.z *= inv; z4.w *= inv;
        for (int o = wid; o < D; o += 32) {
            float4 w = *(const float4*)(fc1W + (size_t)o * D + lane * 4);
            float p = z4.x * w.x + z4.y * w.y + z4.z * w.z + z4.w * w.w;
            #pragma unroll
            for (int off = 16; off > 0; off >>= 1) p += __shfl_xor_sync(0xffffffffu, p, off);
            if (lane == 0) {
                float s = p + fc1b[o];
                s_hz[o] = s > 0.f ? s : 0.2f * s;
            }
        }
        __syncthreads();
    }
    {
        float4 hz4 = *(const float4*)(s_hz + lane * 4);
        for (int j = wid; j < RK * D; j += 32) {
            float4 w = *(const float4*)(fcW + (size_t)j * D + lane * 4);
            float p = hz4.x * w.x + hz4.y * w.y + hz4.z * w.z + hz4.w * w.w;
            #pragma unroll
            for (int off = 16; off > 0; off >>= 1) p += __shfl_xor_sync(0xffffffffu, p, off);
            if (lane == 0) s_wcol[j] = p + fcb[j];
        }
        __syncthreads();
    }
    // fused final: coalesced row GEMV + W_u + update
    {
        float4 hz4 = *(const float4*)(s_hz + lane * 4);
        for (int node = gwarp; node < NN; node += NWARPS) {
            const float* wb = frW + (size_t)node * RK * D;
            float4 wu = make_float4(0.f, 0.f, 0.f, 0.f);
            #pragma unroll
            for (int r = 0; r < RK; r++) {
                float4 w = *(const float4*)(wb + r * D + lane * 4);
                float p = hz4.x * w.x + hz4.y * w.y + hz4.z * w.z + hz4.w * w.w;
                #pragma unroll
                for (int off = 16; off > 0; off >>= 1) p += __shfl_xor_sync(0xffffffffu, p, off);
                float wr = p + frb[(size_t)node * RK + r];
                float4 wc = *(const float4*)(s_wcol + r * D + lane * 4);
                wu.x += wr * wc.x; wu.y += wr * wc.y;
                wu.z += wr * wc.z; wu.w += wr * wc.w;
            }
            float4 iv = *(const float4*)(ini + (size_t)node * D + lane * 4);
            float4 ov;
            ov.x = iv.x + wu.x * iv.x; ov.y = iv.y + wu.y * iv.y;
            ov.z = iv.z + wu.z * iv.z; ov.w = iv.w + wu.w * iv.w;
            *(float4*)(out + (size_t)node * D + lane * 4) = ov;
        }
    }
}

// ---------------- launch ----------------
extern "C" void kernel_launch(void* const* d_in, const int* in_sizes, int n_in,
                              void* d_out, int out_size) {
    const int*   rows  = (const int*)d_in[0];
    const int*   cols  = (const int*)d_in[1];
    const float* vals  = (const float*)d_in[2];
    const float* feats = (const float*)d_in[3];
    const float* gW    = (const float*)d_in[4];
    const float* gb    = (const float*)d_in[5];
    const float* fc1W  = (const float*)d_in[6];
    const float* fc1b  = (const float*)d_in[7];
    const float* frW   = (const float*)d_in[8];
    const float* frb   = (const float*)d_in[9];
    const float* fcW   = (const float*)d_in[10];
    const float* fcb   = (const float*)d_in[11];
    const float* ini   = (const float*)d_in[12];
    float* out = (float*)d_out;

    cudaFuncSetAttribute(k_all, cudaFuncAttributeMaxDynamicSharedMemorySize, SMEM_BYTES);
    k_all<<<NB, 1024, SMEM_BYTES>>>(rows, cols, vals, feats, gW, gb,
                                    fc1W, fc1b, frW, frb, fcW, fcb, ini, out);
}

// round 14
// speedup vs baseline: 1.4545x; 1.4545x over previous
#include <cuda_runtime.h>
#include <cuda_bf16.h>

#define NN 50000
#define D 128
#define LAY 3
#define RK 16
#define NE 1600000
#define NB 148
#define NTHREADS (NB * 1024)
#define NWARPS (NB * 32)
#define CHUNK 338                    // 148*338 = 50024 >= 50000
#define NTILES ((NN + 127) / 128)    // 391
#define SPITCH 136                   // bf16 smem row pitch (272B rows, 16B-aligned)
#define SA_BYTES (128 * SPITCH * 2)  // 34816
#define SMEM_BYTES (2 * SA_BYTES + 512)

__device__ __forceinline__ unsigned bf2_bits(__nv_bfloat162 v) {
    return *reinterpret_cast<unsigned*>(&v);
}

// ---------------- static device scratch ----------------
static __device__ int d_cnt[NN];          // zero at entry (BSS / re-zeroed each run)
static __device__ int d_rowptr[NN + 1];
static __device__ int d_cursor[NN];
static __device__ int d_btot[NB];
static __device__ int d_boff[NB];
static __device__ __align__(16) uint2 d_edge[NE];             // {col, val bits}
static __device__ __align__(16) __nv_bfloat16 d_hb[NN * D];   // h (bf16)
static __device__ __align__(16) float d_zsum[D];

static __device__ unsigned bar_count = 0;
static __device__ volatile unsigned bar_gen = 0;

__device__ __forceinline__ void gridbar() {
    __syncthreads();
    __threadfence();
    if (threadIdx.x == 0) {
        unsigned g = bar_gen;
        if (atomicAdd(&bar_count, 1u) == NB - 1) {
            bar_count = 0;
            __threadfence();
            bar_gen = g + 1;
        } else {
            while (bar_gen == g) { __nanosleep(64); }
        }
    }
    __syncthreads();
    __threadfence();
}

__device__ __forceinline__ float eluf(float t) {
    return t > 0.f ? t : (__expf(t) - 1.f);
}

__device__ __forceinline__ void ldm_x4(unsigned r[4], unsigned addr) {
    asm volatile("ldmatrix.sync.aligned.m8n8.x4.shared.b16 {%0,%1,%2,%3}, [%4];"
                 : "=r"(r[0]), "=r"(r[1]), "=r"(r[2]), "=r"(r[3]) : "r"(addr));
}

__device__ __forceinline__ void mma_bf16(float c[4], const unsigned a[4],
                                         unsigned b0, unsigned b1) {
    asm volatile("mma.sync.aligned.m16n8k16.row.col.f32.bf16.bf16.f32 "
                 "{%0,%1,%2,%3}, {%4,%5,%6,%7}, {%8,%9}, {%0,%1,%2,%3};"
                 : "+f"(c[0]), "+f"(c[1]), "+f"(c[2]), "+f"(c[3])
                 : "r"(a[0]), "r"(a[1]), "r"(a[2]), "r"(a[3]), "r"(b0), "r"(b1));
}

__global__ void __launch_bounds__(1024, 1)
k_all(const int* __restrict__ rows, const int* __restrict__ cols,
      const float* __restrict__ vals, const float* __restrict__ feats,
      const float* __restrict__ gW, const float* __restrict__ gb,
      const float* __restrict__ fc1W, const float* __restrict__ fc1b,
      const float* __restrict__ frW, const float* __restrict__ frb,
      const float* __restrict__ fcW, const float* __restrict__ fcb,
      const float* __restrict__ ini, float* __restrict__ out)
{
    extern __shared__ float sm[];
    __nv_bfloat16* sA = (__nv_bfloat16*)sm;
    __nv_bfloat16* sB = (__nv_bfloat16*)((char*)sm + SA_BYTES);
    float* scol = (float*)((char*)sm + 2 * SA_BYTES);   // 128 floats

    const int tid  = threadIdx.x;
    const int bid  = blockIdx.x;
    const int gtid = bid * 1024 + tid;
    const int lane = tid & 31;
    const int wid  = tid >> 5;
    const int gwarp = bid * 32 + wid;

    // ---------- phase 1: histogram (d_cnt is zero at entry) ----------
    for (int e4 = gtid; e4 < NE / 4; e4 += NTHREADS) {
        int4 r4 = *(const int4*)(rows + e4 * 4);
        atomicAdd(&d_cnt[r4.x], 1);
        atomicAdd(&d_cnt[r4.y], 1);
        atomicAdd(&d_cnt[r4.z], 1);
        atomicAdd(&d_cnt[r4.w], 1);
    }
    gridbar();

    // ---------- scan A (+ zero zsum for this run) ----------
    {
        int* s = (int*)sm;
        int i = bid * CHUNK + tid;
        int v = (tid < CHUNK && i < NN) ? d_cnt[i] : 0;
        s[tid] = v;
        __syncthreads();
        #pragma unroll
        for (int off = 1; off < 1024; off <<= 1) {
            int a = (tid >= off) ? s[tid - off] : 0;
            __syncthreads();
            s[tid] += a;
            __syncthreads();
        }
        if (tid < CHUNK && i < NN) d_rowptr[i] = s[tid] - v;
        if (tid == 0) d_btot[bid] = s[1023];
    }
    if (gtid < D) d_zsum[gtid] = 0.f;
    gridbar();

    // ---------- scan B (block 0) || colsum + feats->bf16 (blocks 1..147) ----------
    if (bid == 0) {
        int* s = (int*)sm;
        int v = (tid < NB) ? d_btot[tid] : 0;
        s[tid] = v;
        __syncthreads();
        #pragma unroll
        for (int off = 1; off < 1024; off <<= 1) {
            int a = (tid >= off) ? s[tid - off] : 0;
            __syncthreads();
            s[tid] += a;
            __syncthreads();
        }
        if (tid < NB) d_boff[tid] = s[tid] - v;
        if (tid == 0) d_rowptr[NN] = s[1023];
    } else {
        if (tid < D) scol[tid] = 0.f;
        __syncthreads();
        float4 cacc = make_float4(0.f, 0.f, 0.f, 0.f);
        int cwarp = (bid - 1) * 32 + wid;
        for (int r = cwarp; r < NN; r += 147 * 32) {
            float4 v = *(const float4*)(feats + (size_t)r * D + lane * 4);
            cacc.x += v.x; cacc.y += v.y; cacc.z += v.z; cacc.w += v.w;
            __nv_bfloat162* dst = (__nv_bfloat162*)(d_hb + (size_t)r * D + lane * 4);
            dst[0] = __floats2bfloat162_rn(v.x, v.y);
            dst[1] = __floats2bfloat162_rn(v.z, v.w);
        }
        atomicAdd(&scol[lane * 4 + 0], cacc.x);
        atomicAdd(&scol[lane * 4 + 1], cacc.y);
        atomicAdd(&scol[lane * 4 + 2], cacc.z);
        atomicAdd(&scol[lane * 4 + 3], cacc.w);
        __syncthreads();
        if (tid < D) atomicAdd(&d_zsum[tid], scol[tid]);
    }
    gridbar();

    // ---------- scan C: finalize rowptr/cursor; re-zero d_cnt for next replay ----------
    {
        int off = d_boff[bid];
        int i = bid * CHUNK + tid;
        if (tid < CHUNK && i < NN) {
            int val = d_rowptr[i] + off;
            d_rowptr[i] = val;
            d_cursor[i] = val;
        }
    }
    for (int i = gtid; i < NN; i += NTHREADS) d_cnt[i] = 0;
    gridbar();

    // ---------- scatter (packed edges) ----------
    for (int e4 = gtid; e4 < NE / 4; e4 += NTHREADS) {
        int4   r4 = *(const int4*)(rows + e4 * 4);
        int4   c4 = *(const int4*)(cols + e4 * 4);
        float4 v4 = *(const float4*)(vals + e4 * 4);
        int p;
        p = atomicAdd(&d_cursor[r4.x], 1); d_edge[p] = make_uint2((unsigned)c4.x, __float_as_uint(v4.x));
        p = atomicAdd(&d_cursor[r4.y], 1); d_edge[p] = make_uint2((unsigned)c4.y, __float_as_uint(v4.y));
        p = atomicAdd(&d_cursor[r4.z], 1); d_edge[p] = make_uint2((unsigned)c4.z, __float_as_uint(v4.z));
        p = atomicAdd(&d_cursor[r4.w], 1); d_edge[p] = make_uint2((unsigned)c4.w, __float_as_uint(v4.w));
    }
    gridbar();

    // ---------- GNN layers: fused SpMM(tile->smem) + tensor-core GEMM ----------
    const unsigned sA_base = (unsigned)__cvta_generic_to_shared(sA);
    const unsigned sB_base = (unsigned)__cvta_generic_to_shared(sB);
    const int wm = wid >> 2, wn = wid & 3;
    const int half = lane >> 4;          // paired-edge gather: 0 = even edge, 1 = odd edge
    const int sub  = lane & 15;          // 16 lanes x 8 cols cover one h row

    for (int l = 0; l < LAY; l++) {
        // W_l -> sB (bf16), block-local
        #pragma unroll
        for (int t = 0; t < 4; t++) {
            int j = tid + t * 1024;          // 4096 groups of 4 floats
            int row = j >> 5, seg = j & 31;
            float4 v = *(const float4*)(gW + (size_t)l * D * D + row * D + seg * 4);
            __nv_bfloat162* dst = (__nv_bfloat162*)(sB + row * SPITCH + seg * 4);
            dst[0] = __floats2bfloat162_rn(v.x, v.y);
            dst[1] = __floats2bfloat162_rn(v.z, v.w);
        }
        if (tid < D) scol[tid] = 0.f;
        float bias[4][2];
        #pragma unroll
        for (int f = 0; f < 4; f++) {
            int nb = wn * 32 + f * 8 + (lane & 3) * 2;
            bias[f][0] = gb[l * D + nb];
            bias[f][1] = gb[l * D + nb + 1];
        }
        __syncthreads();

        for (int tile = bid; tile < NTILES; tile += NB) {
            int rb = tile * 128;

            // --- SpMM: 4 rows per warp; paired-edge LDG.128 gathers into sA ---
            #pragma unroll
            for (int rr = 0; rr < 4; rr++) {
                int lr = wid + rr * 32;
                int row = rb + lr;
                float acc[8];
                #pragma unroll
                for (int k = 0; k < 8; k++) acc[k] = 0.f;
                if (row < NN) {
                    int e0 = d_rowptr[row], e1 = d_rowptr[row + 1];
                    for (int e = e0; e < e1; e += 32) {
                        int idx = e + lane;
                        uint2 ev = make_uint2(0u, 0u);
                        if (idx < e1) ev = d_edge[idx];
                        int nb2 = e1 - e; if (nb2 > 32) nb2 = 32;
                        for (int jb = 0; jb < nb2; jb += 8) {
                            // 8 edges per group: this lane handles edges jb+2u+half (u=0..3)
                            uint4 hv[4]; float vv[4];
                            #pragma unroll
                            for (int u = 0; u < 4; u++) {
                                int src     = jb + 2 * u + half;
                                int c       = __shfl_sync(0xffffffffu, (int)ev.x, src);
                                unsigned vb = __shfl_sync(0xffffffffu, ev.y, src);
                                vv[u] = __uint_as_float(vb);
                                hv[u] = *(const uint4*)(d_hb + (size_t)c * D + sub * 8);
                            }
                            #pragma unroll
                            for (int u = 0; u < 4; u++) {
                                float2 f0 = __bfloat1622float2(*(const __nv_bfloat162*)&hv[u].x);
                                float2 f1 = __bfloat1622float2(*(const __nv_bfloat162*)&hv[u].y);
                                float2 f2 = __bfloat1622float2(*(const __nv_bfloat162*)&hv[u].z);
                                float2 f3 = __bfloat1622float2(*(const __nv_bfloat162*)&hv[u].w);
                                acc[0] += vv[u] * f0.x; acc[1] += vv[u] * f0.y;
                                acc[2] += vv[u] * f1.x; acc[3] += vv[u] * f1.y;
                                acc[4] += vv[u] * f2.x; acc[5] += vv[u] * f2.y;
                                acc[6] += vv[u] * f3.x; acc[7] += vv[u] * f3.y;
                            }
                        }
                    }
                }
                // merge even/odd halves; lanes 0-15 write the row slice
                #pragma unroll
                for (int k = 0; k < 8; k++)
                    acc[k] += __shfl_xor_sync(0xffffffffu, acc[k], 16);
                if (half == 0) {
                    uint4 st;
                    st.x = bf2_bits(__floats2bfloat162_rn(acc[0], acc[1]));
                    st.y = bf2_bits(__floats2bfloat162_rn(acc[2], acc[3]));
                    st.z = bf2_bits(__floats2bfloat162_rn(acc[4], acc[5]));
                    st.w = bf2_bits(__floats2bfloat162_rn(acc[6], acc[7]));
                    *(uint4*)(sA + (size_t)lr * SPITCH + sub * 8) = st;
                }
            }
            __syncthreads();   // sA complete

            // --- GEMM on tile ---
            float c[4][4];
            #pragma unroll
            for (int f = 0; f < 4; f++)
                #pragma unroll
                for (int q = 0; q < 4; q++) c[f][q] = 0.f;

            #pragma unroll
            for (int ks = 0; ks < 8; ks++) {
                int k0 = ks * 16;
                unsigned a[4];
                unsigned aaddr = sA_base +
                    ((wm * 16 + (lane & 15)) * SPITCH + k0 + (lane >> 4) * 8) * 2;
                ldm_x4(a, aaddr);
                #pragma unroll
                for (int hh = 0; hh < 2; hh++) {
                    int nbase = wn * 32 + hh * 16;
                    int grp = lane >> 3;
                    int nrow = nbase + ((grp & 2) << 2) + (lane & 7);
                    int koff = k0 + ((grp & 1) << 3);
                    unsigned b[4];
                    unsigned baddr = sB_base + (nrow * SPITCH + koff) * 2;
                    ldm_x4(b, baddr);
                    mma_bf16(c[hh * 2 + 0], a, b[0], b[1]);
                    mma_bf16(c[hh * 2 + 1], a, b[2], b[3]);
                }
            }
            __syncthreads();   // done reading sA

            // --- epilogue: bias + ELU -> bf16 h, column sums ---
            int r0g = rb + wm * 16 + (lane >> 2);
            int r1g = r0g + 8;
            bool v0 = r0g < NN, v1 = r1g < NN;
            #pragma unroll
            for (int f = 0; f < 4; f++) {
                int nb = wn * 32 + f * 8 + (lane & 3) * 2;
                float o0 = eluf(c[f][0] + bias[f][0]), o1 = eluf(c[f][1] + bias[f][1]);
                float o2 = eluf(c[f][2] + bias[f][0]), o3 = eluf(c[f][3] + bias[f][1]);
                if (v0) *(__nv_bfloat162*)(d_hb + (size_t)r0g * D + nb) =
                            __floats2bfloat162_rn(o0, o1);
                if (v1) *(__nv_bfloat162*)(d_hb + (size_t)r1g * D + nb) =
                            __floats2bfloat162_rn(o2, o3);
                float s0 = (v0 ? o0 : 0.f) + (v1 ? o2 : 0.f);
                float s1 = (v0 ? o1 : 0.f) + (v1 ? o3 : 0.f);
                #pragma unroll
                for (int off = 4; off < 32; off <<= 1) {
                    s0 += __shfl_xor_sync(0xffffffffu, s0, off);
                    s1 += __shfl_xor_sync(0xffffffffu, s1, off);
                }
                if (lane < 4) {
                    atomicAdd(&scol[nb], s0);
                    atomicAdd(&scol[nb + 1], s1);
                }
            }
        }
        __syncthreads();
        if (tid < D) atomicAdd(&d_zsum[tid], scol[tid]);
        gridbar();
    }

    // ---------- tail ----------
    float* s_hz   = sm;
    float* s_wcol = sm + 128;
    {
        const float inv = 1.0f / ((float)(LAY + 1) * (float)NN);
        float4 z4 = *(const float4*)(d_zsum + lane * 4);
        z4.x *= inv; z4.y *= inv; z4.z *= inv; z4.w *= inv;
        for (int o = wid; o < D; o += 32) {
            float4 w = *(const float4*)(fc1W + (size_t)o * D + lane * 4);
            float p = z4.x * w.x + z4.y * w.y + z4.z * w.z + z4.w * w.w;
            #pragma unroll
            for (int off = 16; off > 0; off >>= 1) p += __shfl_xor_sync(0xffffffffu, p, off);
            if (lane == 0) {
                float s = p + fc1b[o];
                s_hz[o] = s > 0.f ? s : 0.2f * s;
            }
        }
        __syncthreads();
    }
    {
        float4 hz4 = *(const float4*)(s_hz + lane * 4);
        for (int j = wid; j < RK * D; j += 32) {
            float4 w = *(const float4*)(fcW + (size_t)j * D + lane * 4);
            float p = hz4.x * w.x + hz4.y * w.y + hz4.z * w.z + hz4.w * w.w;
            #pragma unroll
            for (int off = 16; off > 0; off >>= 1) p += __shfl_xor_sync(0xffffffffu, p, off);
            if (lane == 0) s_wcol[j] = p + fcb[j];
        }
        __syncthreads();
    }
    // fused final: coalesced row GEMV + W_u + update
    {
        float4 hz4 = *(const float4*)(s_hz + lane * 4);
        for (int node = gwarp; node < NN; node += NWARPS) {
            const float* wb = frW + (size_t)node * RK * D;
            float4 wu = make_float4(0.f, 0.f, 0.f, 0.f);
            #pragma unroll
            for (int r = 0; r < RK; r++) {
                float4 w = *(const float4*)(wb + r * D + lane * 4);
                float p = hz4.x * w.x + hz4.y * w.y + hz4.z * w.z + hz4.w * w.w;
                #pragma unroll
                for (int off = 16; off > 0; off >>= 1) p += __shfl_xor_sync(0xffffffffu, p, off);
                float wr = p + frb[(size_t)node * RK + r];
                float4 wc = *(const float4*)(s_wcol + r * D + lane * 4);
                wu.x += wr * wc.x; wu.y += wr * wc.y;
                wu.z += wr * wc.z; wu.w += wr * wc.w;
            }
            float4 iv = *(const float4*)(ini + (size_t)node * D + lane * 4);
            float4 ov;
            ov.x = iv.x + wu.x * iv.x; ov.y = iv.y + wu.y * iv.y;
            ov.z = iv.z + wu.z * iv.z; ov.w = iv.w + wu.w * iv.w;
            *(float4*)(out + (size_t)node * D + lane * 4) = ov;
        }
    }
}

// ---------------- launch ----------------
extern "C" void kernel_launch(void* const* d_in, const int* in_sizes, int n_in,
                              void* d_out, int out_size) {
    const int*   rows  = (const int*)d_in[0];
    const int*   cols  = (const int*)d_in[1];
    const float* vals  = (const float*)d_in[2];
    const float* feats = (const float*)d_in[3];
    const float* gW    = (const float*)d_in[4];
    const float* gb    = (const float*)d_in[5];
    const float* fc1W  = (const float*)d_in[6];
    const float* fc1b  = (const float*)d_in[7];
    const float* frW   = (const float*)d_in[8];
    const float* frb   = (const float*)d_in[9];
    const float* fcW   = (const float*)d_in[10];
    const float* fcb   = (const float*)d_in[11];
    const float* ini   = (const float*)d_in[12];
    float* out = (float*)d_out;

    cudaFuncSetAttribute(k_all, cudaFuncAttributeMaxDynamicSharedMemorySize, SMEM_BYTES);
    k_all<<<NB, 1024, SMEM_BYTES>>>(rows, cols, vals, feats, gW, gb,
                                    fc1W, fc1b, frW, frb, fcW, fcb, ini, out);
}